// round 4
// baseline (speedup 1.0000x reference)
#include <cuda_runtime.h>
#include <math_constants.h>

// Problem constants (fixed by the reference)
#define BB 128
#define SS 4096
#define MM 20
#define NROWS (BB * SS)            // 524288
#define THREADS 256
#define NBLOCKS (NROWS / THREADS)  // 2048 (exact)

// Scratch for deterministic two-stage reduction (no cudaMalloc allowed)
__device__ double g_partials[NBLOCKS];

__global__ __launch_bounds__(THREADS, 2)
void sketch_main_kernel(const float* __restrict__ xs,
                        const float* __restrict__ logits,
                        const float* __restrict__ mus,
                        const float* __restrict__ sigmas,
                        const float* __restrict__ pen_pred)
{
    const float LOG_2PI = 1.8378770664093453f;
    const float INV_N   = 1.0f / (float)NROWS;

    const int r = blockIdx.x * THREADS + threadIdx.x;   // row id = b*S + s

    // ---- xs: current row (5 floats) + previous row's position (2 floats) ----
    const float* xr = xs + (size_t)r * 5;
    const float x0 = xr[0];
    const float x1 = xr[1];
    const float p0 = xr[2];
    const float p1 = xr[3];
    const float p2 = xr[4];

    float rel0 = x0, rel1 = x1;
    if ((r & (SS - 1)) != 0) {      // s > 0 -> previous row is r-1 (same batch)
        rel0 -= xr[-5];
        rel1 -= xr[-4];
    }

    // ---- vectorized row bases (all 16B aligned: 80/160/240 B row strides) ----
    const float4* lg4 = (const float4*)(logits + (size_t)r * 20); // 5 x float4
    const float4* mu4 = (const float4*)(mus    + (size_t)r * 40); // 10 x float4
    const float4* sg4 = (const float4*)(sigmas + (size_t)r * 60); // 15 x float4

    float a[MM];   // logits + comp_logp
    float l[MM];   // logits
    float maxA = -CUDART_INF_F;
    float maxL = -CUDART_INF_F;

    #pragma unroll
    for (int i = 0; i < 5; i++) {   // 4 mixture components per iteration
        const float4 lg = lg4[i];
        const float4 m0 = mu4[2 * i];
        const float4 m1 = mu4[2 * i + 1];
        const float4 s0 = sg4[3 * i];
        const float4 s1 = sg4[3 * i + 1];
        const float4 s2 = sg4[3 * i + 2];

        // de-interleave 4 components (layout checked against row-major refs)
        const float mu0[4] = {m0.x, m0.z, m1.x, m1.z};
        const float mu1[4] = {m0.y, m0.w, m1.y, m1.w};
        const float l00[4] = {s0.x, s0.w, s1.z, s2.y};
        const float l10[4] = {s0.y, s1.x, s1.w, s2.z};
        const float l11[4] = {s0.z, s1.y, s2.x, s2.w};
        const float lgv[4] = {lg.x, lg.y, lg.z, lg.w};

        #pragma unroll
        for (int j = 0; j < 4; j++) {
            const int m = 4 * i + j;
            const float d0 = rel0 - mu0[j];
            const float d1 = rel1 - mu1[j];
            const float z0 = __fdividef(d0, l00[j]);
            const float z1 = __fdividef(fmaf(-l10[j], z0, d1), l11[j]);
            const float clp = fmaf(-0.5f, fmaf(z0, z0, z1 * z1), -LOG_2PI)
                              - __logf(l00[j] * l11[j]);
            const float av = lgv[j] + clp;
            a[m] = av;
            l[m] = lgv[j];
            maxA = fmaxf(maxA, av);
            maxL = fmaxf(maxL, lgv[j]);
        }
    }

    float sumA = 0.0f, sumL = 0.0f;
    #pragma unroll
    for (int m = 0; m < MM; m++) {
        sumA += __expf(a[m] - maxA);
        sumL += __expf(l[m] - maxL);
    }
    // mix_logp = LSE(logits + comp) - LSE(logits)   (exact two-pass, as reference)
    const float mix_logp = (maxA + __logf(sumA)) - (maxL + __logf(sumL));

    // ---- pen term: -sum(pen_pred * log_softmax(pen_true)), averaged ----
    const float mp  = fmaxf(p0, fmaxf(p1, p2));
    const float lse = mp + __logf(__expf(p0 - mp) + __expf(p1 - mp) + __expf(p2 - mp));
    const float* pr = pen_pred + (size_t)r * 3;
    const float pen_c = -(pr[0] * (p0 - lse) + pr[1] * (p1 - lse) + pr[2] * (p2 - lse));

    const float v = -mix_logp + pen_c * INV_N;

    // ---- deterministic block reduction (double) ----
    double dv = (double)v;
    #pragma unroll
    for (int off = 16; off > 0; off >>= 1)
        dv += __shfl_down_sync(0xffffffffu, dv, off);

    __shared__ double ws[THREADS / 32];
    const int lane = threadIdx.x & 31;
    const int wid  = threadIdx.x >> 5;
    if (lane == 0) ws[wid] = dv;
    __syncthreads();
    if (wid == 0) {
        double t = (lane < THREADS / 32) ? ws[lane] : 0.0;
        #pragma unroll
        for (int off = 4; off > 0; off >>= 1)
            t += __shfl_down_sync(0xffffffffu, t, off);
        if (lane == 0) g_partials[blockIdx.x] = t;
    }
}

__global__ void sketch_reduce_kernel(float* __restrict__ out)
{
    __shared__ double sm[256];
    double t = 0.0;
    for (int i = threadIdx.x; i < NBLOCKS; i += 256)
        t += g_partials[i];
    sm[threadIdx.x] = t;
    __syncthreads();
    #pragma unroll
    for (int off = 128; off > 0; off >>= 1) {
        if (threadIdx.x < off) sm[threadIdx.x] += sm[threadIdx.x + off];
        __syncthreads();
    }
    if (threadIdx.x == 0) out[0] = (float)sm[0];
}

extern "C" void kernel_launch(void* const* d_in, const int* in_sizes, int n_in,
                              void* d_out, int out_size)
{
    (void)in_sizes; (void)n_in; (void)out_size;
    const float* xs      = (const float*)d_in[0];
    const float* logits  = (const float*)d_in[1];
    const float* mus     = (const float*)d_in[2];
    const float* sigmas  = (const float*)d_in[3];
    const float* pen     = (const float*)d_in[4];
    float* out = (float*)d_out;

    sketch_main_kernel<<<NBLOCKS, THREADS>>>(xs, logits, mus, sigmas, pen);
    sketch_reduce_kernel<<<1, 256>>>(out);
}